// round 7
// baseline (speedup 1.0000x reference)
#include <cuda_runtime.h>
#include <cstdint>

// ----------------------------------------------------------------------------
// ResBlock_71021579207010 — GB300 (sm_103a) — fully fused single kernel.
//
// Math: ste_sign(relu(.)) == +1 -> conv1/bn1 dead; conv2 output is a
// per-channel constant (t<16 pad variant vs t>=16). Remaining work:
//   out[b,t,f] = relu( c[f] + sum_c sign(x[b,t,c])*sign(w_sc[c,f]) )
// via ballot-packed bits + xor/popc: dot = 128 - 2*popc(px^pw).
//
// R4 postmortem: each extra grid launch costs ~5us wall; 3 launches regressed.
// R5: single kernel. Blocks 0..36 (wave-1 guaranteed) build the packed weights
// and bn constants, publish via threadfence+flag; all blocks prefetch x rows,
// spin briefly, then run the R3-proven row loop. Sync vars self-reset so every
// graph replay is identical.  (R6/R7: resubmits, broker timeouts, no data.)
// ----------------------------------------------------------------------------

__device__ int g_partial[32][128];                  // per-block sign counts of w2
__device__ __align__(16) unsigned g_pw[128][4];     // packed sign bits of w_sc
__device__ __align__(16) float    g_add_ge[128];    // relu(bn2(S0+S1)) + 128
__device__ __align__(16) float    g_add_lt[128];    // relu(bn2(S1))    + 128
__device__ int g_pcount = 0;   // prologue chores done (0..36)
__device__ int g_flag   = 0;   // constants ready
__device__ int g_exit   = 0;   // blocks finished (for reset)

// Per-row compute: v = 4 channels/lane of one row; returns relu(c + dot).
__device__ __forceinline__ float4 row_body(const float4& v, bool lt, int lane,
                                           const uint4& pw0, const uint4& pw1,
                                           const uint4& pw2, const uint4& pw3,
                                           const float4& age, const float4& alt)
{
    const unsigned px0 = __ballot_sync(0xffffffffu, v.x >= 0.f);
    const unsigned px1 = __ballot_sync(0xffffffffu, v.y >= 0.f);
    const unsigned px2 = __ballot_sync(0xffffffffu, v.z >= 0.f);
    const unsigned px3 = __ballot_sync(0xffffffffu, v.w >= 0.f);

    const float a0 = lt ? alt.x : age.x;
    const float a1 = lt ? alt.y : age.y;
    const float a2 = lt ? alt.z : age.z;
    const float a3 = lt ? alt.w : age.w;

    const int pc0 = __popc(px0 ^ pw0.x) + __popc(px1 ^ pw0.y)
                  + __popc(px2 ^ pw0.z) + __popc(px3 ^ pw0.w);
    const int pc1 = __popc(px0 ^ pw1.x) + __popc(px1 ^ pw1.y)
                  + __popc(px2 ^ pw1.z) + __popc(px3 ^ pw1.w);
    const int pc2 = __popc(px0 ^ pw2.x) + __popc(px1 ^ pw2.y)
                  + __popc(px2 ^ pw2.z) + __popc(px3 ^ pw2.w);
    const int pc3 = __popc(px0 ^ pw3.x) + __popc(px1 ^ pw3.y)
                  + __popc(px2 ^ pw3.z) + __popc(px3 ^ pw3.w);

    float4 o;
    o.x = fmaxf(fmaf(-2.f, (float)pc0, a0), 0.f);
    o.y = fmaxf(fmaf(-2.f, (float)pc1, a1), 0.f);
    o.z = fmaxf(fmaf(-2.f, (float)pc2, a2), 0.f);
    o.w = fmaxf(fmaf(-2.f, (float)pc3, a3), 0.f);
    return o;
}

__global__ void __launch_bounds__(256) resblock_fused(
    const float* __restrict__ x,
    float* __restrict__ out,
    const float* __restrict__ w2,
    const float* __restrict__ w_sc,
    const float* __restrict__ beta2,
    const float* __restrict__ mean2,
    const float* __restrict__ var2)
{
    const int bid  = blockIdx.x;
    const int tid  = threadIdx.x;
    const int lane = tid & 31;
    const int warp = tid >> 5;

    __shared__ int sc[2][128];

    // ---------------- prologue chores (blocks 0..36, all wave-1) -----------
    if (bid < 32) {
        // Sign-count 8 flattened (k,c)-rows m = bid*8 .. bid*8+7 of w2.
        const int f = tid & 127;
        const int h = tid >> 7;              // 0/1: 4 rows each
        const int m0 = bid * 8 + h * 4;
        int cnt = 0;
        #pragma unroll
        for (int i = 0; i < 4; ++i)
            cnt += (w2[(m0 + i) * 128 + f] >= 0.f) ? 1 : 0;
        sc[h][f] = cnt;
        __syncthreads();
        if (tid < 128) g_partial[bid][tid] = sc[0][tid] + sc[1][tid];
        __threadfence();
        __syncthreads();
        if (tid == 0) atomicAdd(&g_pcount, 1);
    } else if (bid < 36) {
        // Pack w_sc sign word j: bit l <-> channel c = 4*l + j (ballot order).
        const int j = bid - 32;
        if (tid < 128) {
            const int f = tid;
            unsigned p = 0u;
            #pragma unroll
            for (int l = 0; l < 32; ++l)
                if (w_sc[(4 * l + j) * 128 + f] >= 0.f) p |= (1u << l);
            g_pw[f][j] = p;
            __threadfence();
        }
        __syncthreads();
        if (tid == 0) atomicAdd(&g_pcount, 1);
    } else if (bid == 36) {
        // Wait for the 36 chores, fold bn2 constants, publish flag.
        if (tid == 0) {
            volatile int* pc = &g_pcount;
            while (*pc != 36) __nanosleep(128);
            __threadfence();                 // acquire: invalidate L1
        }
        __syncthreads();
        if (tid < 128) {
            const int f = tid;
            int t0 = 0, t1 = 0;
            #pragma unroll
            for (int s = 0; s < 16; ++s)  t0 += g_partial[s][f];
            #pragma unroll
            for (int s = 16; s < 32; ++s) t1 += g_partial[s][f];
            const float S0 = 2.f * (float)t0 - 128.f;   // sum of signs, k=0
            const float S1 = 2.f * (float)t1 - 128.f;   // k=1
            const float inv = rsqrtf(var2[f] + 1e-3f);
            const float cge = fmaxf(fmaf(S0 + S1 - mean2[f], inv, beta2[f]), 0.f);
            const float clt = fmaxf(fmaf(S1      - mean2[f], inv, beta2[f]), 0.f);
            g_add_ge[f] = cge + 128.f;       // fold "+128" of dot = 128 - 2*pc
            g_add_lt[f] = clt + 128.f;
            __threadfence();
        }
        __syncthreads();
        if (tid == 0) atomicExch(&g_flag, 1);
    }

    // ---------------- worker path (all 2048 blocks) ------------------------
    const int f0 = 4 * lane;
    const size_t row0 = (size_t)bid * 128 + (size_t)warp * 16;

    // Prefetch first 4 rows while (possibly) waiting on the flag.
    float4 pre[4];
    #pragma unroll
    for (int r = 0; r < 4; ++r)
        pre[r] = reinterpret_cast<const float4*>(x + (row0 + r) * 128)[lane];

    if (tid == 0) {
        volatile int* fl = &g_flag;
        while (*fl == 0) __nanosleep(1024);
        __threadfence();                     // acquire: invalidate L1
    }
    __syncthreads();

    // Row-invariant weights/constants into registers.
    const uint4 pw0 = *reinterpret_cast<const uint4*>(g_pw[f0 + 0]);
    const uint4 pw1 = *reinterpret_cast<const uint4*>(g_pw[f0 + 1]);
    const uint4 pw2 = *reinterpret_cast<const uint4*>(g_pw[f0 + 2]);
    const uint4 pw3 = *reinterpret_cast<const uint4*>(g_pw[f0 + 3]);
    const float4 age = *reinterpret_cast<const float4*>(&g_add_ge[f0]);
    const float4 alt = *reinterpret_cast<const float4*>(&g_add_lt[f0]);

    // Rows with t<16 exist only in warp 0 of every 64th block (8192/128=64).
    const bool has_lt = (warp == 0) && ((bid & 63) == 0);

    if (has_lt) {
        #pragma unroll
        for (int r = 0; r < 4; ++r) {
            const size_t row = row0 + r;
            const bool lt = ((row & 8191u) < 16u);
            reinterpret_cast<float4*>(out + row * 128)[lane] =
                row_body(pre[r], lt, lane, pw0, pw1, pw2, pw3, age, alt);
        }
        #pragma unroll 6
        for (int r = 4; r < 16; ++r) {
            const size_t row = row0 + r;
            const float4 v = reinterpret_cast<const float4*>(x + row * 128)[lane];
            const bool lt = ((row & 8191u) < 16u);
            reinterpret_cast<float4*>(out + row * 128)[lane] =
                row_body(v, lt, lane, pw0, pw1, pw2, pw3, age, alt);
        }
    } else {
        #pragma unroll
        for (int r = 0; r < 4; ++r) {
            const size_t row = row0 + r;
            reinterpret_cast<float4*>(out + row * 128)[lane] =
                row_body(pre[r], false, lane, pw0, pw1, pw2, pw3, age, alt);
        }
        #pragma unroll 6
        for (int r = 4; r < 16; ++r) {
            const size_t row = row0 + r;
            const float4 v = reinterpret_cast<const float4*>(x + row * 128)[lane];
            reinterpret_cast<float4*>(out + row * 128)[lane] =
                row_body(v, false, lane, pw0, pw1, pw2, pw3, age, alt);
        }
    }

    // ---------------- reset protocol (deterministic graph replays) ---------
    if (tid == 0) {
        const int n = atomicAdd(&g_exit, 1);
        if (n == (int)gridDim.x - 1) {       // last block: restore sync state
            g_pcount = 0;
            g_flag   = 0;
            __threadfence();
            g_exit   = 0;
        }
    }
}

extern "C" void kernel_launch(void* const* d_in, const int* in_sizes, int n_in,
                              void* d_out, int out_size)
{
    // metadata order: x, w1, w2, w_sc, beta1, mean1, var1, beta2, mean2, var2
    const float* x     = (const float*)d_in[0];
    const float* w2    = (const float*)d_in[2];
    const float* w_sc  = (const float*)d_in[3];
    const float* beta2 = (const float*)d_in[7];
    const float* mean2 = (const float*)d_in[8];
    const float* var2  = (const float*)d_in[9];
    float* out = (float*)d_out;

    // 262144 rows / 128 rows per block = 2048 blocks, one launch total.
    resblock_fused<<<2048, 256>>>(x, out, w2, w_sc, beta2, mean2, var2);
}

// round 10
// speedup vs baseline: 1.0680x; 1.0680x over previous
#include <cuda_runtime.h>
#include <cstdint>

// ----------------------------------------------------------------------------
// ResBlock_71021579207010 — GB300 (sm_103a) — fused single kernel, reg-lean.
//
// Math: ste_sign(relu(.)) == +1 -> conv1/bn1 dead; conv2 output is a
// per-channel constant (t<16 pad variant vs t>=16). Remaining work:
//   out[b,t,f] = relu( c[f] + sum_c sign(x[b,t,c])*sign(w_sc[c,f]) )
// via ballot-packed bits + xor/popc: dot = 128 - 2*popc(px^pw).
//
// R7 postmortem: fusion worked (1 launch, ~6.8us overhead) but the float4
// prefetch array + prologue paths pushed regs 48->68, occ 52->34%, DRAM
// 66->51%. R8: zero-register L2 prefetch (prefetch.global.L2), cap
// launch_bounds(256,5) (<=51 regs), worker loop identical to R3's 48-reg body.
// (R9/R10: resubmits, broker timeouts, no data.)
// ----------------------------------------------------------------------------

__device__ int g_partial[32][128];                  // per-block sign counts of w2
__device__ __align__(16) unsigned g_pw[128][4];     // packed sign bits of w_sc
__device__ __align__(16) float    g_add_ge[128];    // relu(bn2(S0+S1)) + 128
__device__ __align__(16) float    g_add_lt[128];    // relu(bn2(S1))    + 128
__device__ int g_pcount = 0;   // prologue chores done (0..36)
__device__ int g_flag   = 0;   // constants ready
__device__ int g_exit   = 0;   // blocks finished (for reset)

// Row-loop body shared by both paths (R3-proven). HAS_LT = pad handling.
template <bool HAS_LT>
__device__ __forceinline__ void do_rows(const float* __restrict__ x,
                                        float* __restrict__ out,
                                        size_t row0, int lane,
                                        const uint4& pw0, const uint4& pw1,
                                        const uint4& pw2, const uint4& pw3,
                                        const float4& age, const float4& alt)
{
    #pragma unroll 4
    for (int r = 0; r < 16; ++r) {
        const size_t row = row0 + r;

        // 128 floats of this row: lane reads channels [4*lane, 4*lane+3].
        const float4 v = reinterpret_cast<const float4*>(x + row * 128)[lane];

        // Pack row sign bits: word j, bit l = sign(x[4l + j])  (>=0 -> 1).
        const unsigned px0 = __ballot_sync(0xffffffffu, v.x >= 0.f);
        const unsigned px1 = __ballot_sync(0xffffffffu, v.y >= 0.f);
        const unsigned px2 = __ballot_sync(0xffffffffu, v.z >= 0.f);
        const unsigned px3 = __ballot_sync(0xffffffffu, v.w >= 0.f);

        float a0, a1, a2, a3;
        if (HAS_LT) {
            const bool lt = ((row & 8191u) < 16u);  // conv2 causal pad region
            a0 = lt ? alt.x : age.x;
            a1 = lt ? alt.y : age.y;
            a2 = lt ? alt.z : age.z;
            a3 = lt ? alt.w : age.w;
        } else {
            a0 = age.x; a1 = age.y; a2 = age.z; a3 = age.w;
        }

        const int pc0 = __popc(px0 ^ pw0.x) + __popc(px1 ^ pw0.y)
                      + __popc(px2 ^ pw0.z) + __popc(px3 ^ pw0.w);
        const int pc1 = __popc(px0 ^ pw1.x) + __popc(px1 ^ pw1.y)
                      + __popc(px2 ^ pw1.z) + __popc(px3 ^ pw1.w);
        const int pc2 = __popc(px0 ^ pw2.x) + __popc(px1 ^ pw2.y)
                      + __popc(px2 ^ pw2.z) + __popc(px3 ^ pw2.w);
        const int pc3 = __popc(px0 ^ pw3.x) + __popc(px1 ^ pw3.y)
                      + __popc(px2 ^ pw3.z) + __popc(px3 ^ pw3.w);

        float4 o;
        o.x = fmaxf(fmaf(-2.f, (float)pc0, a0), 0.f);
        o.y = fmaxf(fmaf(-2.f, (float)pc1, a1), 0.f);
        o.z = fmaxf(fmaf(-2.f, (float)pc2, a2), 0.f);
        o.w = fmaxf(fmaf(-2.f, (float)pc3, a3), 0.f);

        reinterpret_cast<float4*>(out + row * 128)[lane] = o;
    }
}

__global__ void __launch_bounds__(256, 5) resblock_fused(
    const float* __restrict__ x,
    float* __restrict__ out,
    const float* __restrict__ w2,
    const float* __restrict__ w_sc,
    const float* __restrict__ beta2,
    const float* __restrict__ mean2,
    const float* __restrict__ var2)
{
    const int bid  = blockIdx.x;
    const int tid  = threadIdx.x;
    const int lane = tid & 31;
    const int warp = tid >> 5;

    __shared__ int sc[2][128];

    // ---------------- prologue chores (blocks 0..36, all wave-1) -----------
    if (bid < 32) {
        // Sign-count 8 flattened (k,c)-rows m = bid*8 .. bid*8+7 of w2.
        const int f = tid & 127;
        const int h = tid >> 7;              // 0/1: 4 rows each
        const int m0 = bid * 8 + h * 4;
        int cnt = 0;
        #pragma unroll
        for (int i = 0; i < 4; ++i)
            cnt += (w2[(m0 + i) * 128 + f] >= 0.f) ? 1 : 0;
        sc[h][f] = cnt;
        __syncthreads();
        if (tid < 128) g_partial[bid][tid] = sc[0][tid] + sc[1][tid];
        __threadfence();
        __syncthreads();
        if (tid == 0) atomicAdd(&g_pcount, 1);
    } else if (bid < 36) {
        // Pack w_sc sign word j: bit l <-> channel c = 4*l + j (ballot order).
        const int j = bid - 32;
        if (tid < 128) {
            const int f = tid;
            unsigned p = 0u;
            #pragma unroll
            for (int l = 0; l < 32; ++l)
                if (w_sc[(4 * l + j) * 128 + f] >= 0.f) p |= (1u << l);
            g_pw[f][j] = p;
            __threadfence();
        }
        __syncthreads();
        if (tid == 0) atomicAdd(&g_pcount, 1);
    } else if (bid == 36) {
        // Wait for the 36 chores, fold bn2 constants, publish flag.
        if (tid == 0) {
            volatile int* pc = &g_pcount;
            while (*pc != 36) __nanosleep(128);
            __threadfence();                 // acquire: invalidate L1
        }
        __syncthreads();
        if (tid < 128) {
            const int f = tid;
            int t0 = 0, t1 = 0;
            #pragma unroll
            for (int s = 0; s < 16; ++s)  t0 += g_partial[s][f];
            #pragma unroll
            for (int s = 16; s < 32; ++s) t1 += g_partial[s][f];
            const float S0 = 2.f * (float)t0 - 128.f;   // sum of signs, k=0
            const float S1 = 2.f * (float)t1 - 128.f;   // k=1
            const float inv = rsqrtf(var2[f] + 1e-3f);
            const float cge = fmaxf(fmaf(S0 + S1 - mean2[f], inv, beta2[f]), 0.f);
            const float clt = fmaxf(fmaf(S1      - mean2[f], inv, beta2[f]), 0.f);
            g_add_ge[f] = cge + 128.f;       // fold "+128" of dot = 128 - 2*pc
            g_add_lt[f] = clt + 128.f;
            __threadfence();
        }
        __syncthreads();
        if (tid == 0) atomicExch(&g_flag, 1);
    }

    // ---------------- worker path (all 2048 blocks) ------------------------
    const int f0 = 4 * lane;
    const size_t row0 = (size_t)bid * 128 + (size_t)warp * 16;

    // Zero-register L2 prefetch of this warp's first 8 rows (hides DRAM
    // latency behind the flag spin without inflating the register budget).
    {
        const float* p = x + row0 * 128 + 4 * lane;
        #pragma unroll
        for (int r = 0; r < 8; ++r)
            asm volatile("prefetch.global.L2 [%0];" :: "l"(p + r * 128));
    }

    if (tid == 0) {
        volatile int* fl = &g_flag;
        while (*fl == 0) __nanosleep(256);
        __threadfence();                     // acquire: invalidate L1
    }
    __syncthreads();

    // Row-invariant weights/constants into registers.
    const uint4 pw0 = *reinterpret_cast<const uint4*>(g_pw[f0 + 0]);
    const uint4 pw1 = *reinterpret_cast<const uint4*>(g_pw[f0 + 1]);
    const uint4 pw2 = *reinterpret_cast<const uint4*>(g_pw[f0 + 2]);
    const uint4 pw3 = *reinterpret_cast<const uint4*>(g_pw[f0 + 3]);
    const float4 age = *reinterpret_cast<const float4*>(&g_add_ge[f0]);
    const float4 alt = *reinterpret_cast<const float4*>(&g_add_lt[f0]);

    // Rows with t<16 exist only in warp 0 of every 64th block (8192/128=64).
    if (warp == 0 && (bid & 63) == 0) {
        do_rows<true >(x, out, row0, lane, pw0, pw1, pw2, pw3, age, alt);
    } else {
        do_rows<false>(x, out, row0, lane, pw0, pw1, pw2, pw3, age, alt);
    }

    // ---------------- reset protocol (deterministic graph replays) ---------
    if (tid == 0) {
        const int n = atomicAdd(&g_exit, 1);
        if (n == (int)gridDim.x - 1) {       // last block: restore sync state
            g_pcount = 0;
            g_flag   = 0;
            __threadfence();
            g_exit   = 0;
        }
    }
}

extern "C" void kernel_launch(void* const* d_in, const int* in_sizes, int n_in,
                              void* d_out, int out_size)
{
    // metadata order: x, w1, w2, w_sc, beta1, mean1, var1, beta2, mean2, var2
    const float* x     = (const float*)d_in[0];
    const float* w2    = (const float*)d_in[2];
    const float* w_sc  = (const float*)d_in[3];
    const float* beta2 = (const float*)d_in[7];
    const float* mean2 = (const float*)d_in[8];
    const float* var2  = (const float*)d_in[9];
    float* out = (float*)d_out;

    // 262144 rows / 128 rows per block = 2048 blocks, one launch total.
    resblock_fused<<<2048, 256>>>(x, out, w2, w_sc, beta2, mean2, var2);
}

// round 11
// speedup vs baseline: 1.1446x; 1.0717x over previous
#include <cuda_runtime.h>
#include <cstdint>

// ----------------------------------------------------------------------------
// ResBlock_71021579207010 — GB300 (sm_103a) — fused single kernel, v3.
//
// Math: ste_sign(relu(.)) == +1 -> conv1/bn1 dead; conv2 output is a
// per-channel constant (t<16 pad variant vs t>=16). Remaining work:
//   out[b,t,f] = relu( c[f] + sum_c sign(x[b,t,c])*sign(w_sc[c,f]) )
// via ballot-packed bits + xor/popc: dot = 128 - 2*popc(px^pw).
//
// R10 postmortem: fused kernel is 54us at BOTH occ 34% and occ 54% -> the
// ~12us penalty vs R3's 41.7us streaming kernel is occupancy-invariant fixed
// time. Suspect: __nanosleep spin granularity (us-scale oversleep at NAT
// clock) + 2048 CCTL.IVALL L1 flushes from consumer __threadfence + useless
// prefetch. R11: tight ld.acquire.gpu polling (no nanosleep), acquire-load
// instead of consumer fence, prefetch deleted.
// ----------------------------------------------------------------------------

__device__ int g_partial[32][128];                  // per-block sign counts of w2
__device__ __align__(16) unsigned g_pw[128][4];     // packed sign bits of w_sc
__device__ __align__(16) float    g_add_ge[128];    // relu(bn2(S0+S1)) + 128
__device__ __align__(16) float    g_add_lt[128];    // relu(bn2(S1))    + 128
__device__ int g_pcount = 0;   // prologue chores done (0..36)
__device__ int g_flag   = 0;   // constants ready
__device__ int g_exit   = 0;   // blocks finished (for reset)

// Acquire load from global (gpu scope) — poll primitive, no L1 flush needed.
__device__ __forceinline__ int ld_acquire_gpu(const int* p)
{
    int v;
    asm volatile("ld.acquire.gpu.b32 %0, [%1];" : "=r"(v) : "l"(p) : "memory");
    return v;
}

// Row-loop body shared by both paths (R3-proven). HAS_LT = pad handling.
template <bool HAS_LT>
__device__ __forceinline__ void do_rows(const float* __restrict__ x,
                                        float* __restrict__ out,
                                        size_t row0, int lane,
                                        const uint4& pw0, const uint4& pw1,
                                        const uint4& pw2, const uint4& pw3,
                                        const float4& age, const float4& alt)
{
    #pragma unroll 4
    for (int r = 0; r < 16; ++r) {
        const size_t row = row0 + r;

        // 128 floats of this row: lane reads channels [4*lane, 4*lane+3].
        const float4 v = reinterpret_cast<const float4*>(x + row * 128)[lane];

        // Pack row sign bits: word j, bit l = sign(x[4l + j])  (>=0 -> 1).
        const unsigned px0 = __ballot_sync(0xffffffffu, v.x >= 0.f);
        const unsigned px1 = __ballot_sync(0xffffffffu, v.y >= 0.f);
        const unsigned px2 = __ballot_sync(0xffffffffu, v.z >= 0.f);
        const unsigned px3 = __ballot_sync(0xffffffffu, v.w >= 0.f);

        float a0, a1, a2, a3;
        if (HAS_LT) {
            const bool lt = ((row & 8191u) < 16u);  // conv2 causal pad region
            a0 = lt ? alt.x : age.x;
            a1 = lt ? alt.y : age.y;
            a2 = lt ? alt.z : age.z;
            a3 = lt ? alt.w : age.w;
        } else {
            a0 = age.x; a1 = age.y; a2 = age.z; a3 = age.w;
        }

        const int pc0 = __popc(px0 ^ pw0.x) + __popc(px1 ^ pw0.y)
                      + __popc(px2 ^ pw0.z) + __popc(px3 ^ pw0.w);
        const int pc1 = __popc(px0 ^ pw1.x) + __popc(px1 ^ pw1.y)
                      + __popc(px2 ^ pw1.z) + __popc(px3 ^ pw1.w);
        const int pc2 = __popc(px0 ^ pw2.x) + __popc(px1 ^ pw2.y)
                      + __popc(px2 ^ pw2.z) + __popc(px3 ^ pw2.w);
        const int pc3 = __popc(px0 ^ pw3.x) + __popc(px1 ^ pw3.y)
                      + __popc(px2 ^ pw3.z) + __popc(px3 ^ pw3.w);

        float4 o;
        o.x = fmaxf(fmaf(-2.f, (float)pc0, a0), 0.f);
        o.y = fmaxf(fmaf(-2.f, (float)pc1, a1), 0.f);
        o.z = fmaxf(fmaf(-2.f, (float)pc2, a2), 0.f);
        o.w = fmaxf(fmaf(-2.f, (float)pc3, a3), 0.f);

        reinterpret_cast<float4*>(out + row * 128)[lane] = o;
    }
}

__global__ void __launch_bounds__(256, 5) resblock_fused(
    const float* __restrict__ x,
    float* __restrict__ out,
    const float* __restrict__ w2,
    const float* __restrict__ w_sc,
    const float* __restrict__ beta2,
    const float* __restrict__ mean2,
    const float* __restrict__ var2)
{
    const int bid  = blockIdx.x;
    const int tid  = threadIdx.x;
    const int lane = tid & 31;
    const int warp = tid >> 5;

    __shared__ int sc[2][128];

    // ---------------- prologue chores (blocks 0..36, all wave-1) -----------
    if (bid < 32) {
        // Sign-count 8 flattened (k,c)-rows m = bid*8 .. bid*8+7 of w2.
        const int f = tid & 127;
        const int h = tid >> 7;              // 0/1: 4 rows each
        const int m0 = bid * 8 + h * 4;
        int cnt = 0;
        #pragma unroll
        for (int i = 0; i < 4; ++i)
            cnt += (w2[(m0 + i) * 128 + f] >= 0.f) ? 1 : 0;
        sc[h][f] = cnt;
        __syncthreads();
        if (tid < 128) g_partial[bid][tid] = sc[0][tid] + sc[1][tid];
        __threadfence();                     // release partials
        __syncthreads();
        if (tid == 0) atomicAdd(&g_pcount, 1);
    } else if (bid < 36) {
        // Pack w_sc sign word j: bit l <-> channel c = 4*l + j (ballot order).
        const int j = bid - 32;
        if (tid < 128) {
            const int f = tid;
            unsigned p = 0u;
            #pragma unroll
            for (int l = 0; l < 32; ++l)
                if (w_sc[(4 * l + j) * 128 + f] >= 0.f) p |= (1u << l);
            g_pw[f][j] = p;
            __threadfence();                 // release packed bits
        }
        __syncthreads();
        if (tid == 0) atomicAdd(&g_pcount, 1);
    } else if (bid == 36) {
        // Wait for the 36 chores, fold bn2 constants, publish flag.
        if (tid == 0) {
            while (ld_acquire_gpu(&g_pcount) != 36) { }
        }
        __syncthreads();
        if (tid < 128) {
            const int f = tid;
            int t0 = 0, t1 = 0;
            #pragma unroll
            for (int s = 0; s < 16; ++s)  t0 += g_partial[s][f];
            #pragma unroll
            for (int s = 16; s < 32; ++s) t1 += g_partial[s][f];
            const float S0 = 2.f * (float)t0 - 128.f;   // sum of signs, k=0
            const float S1 = 2.f * (float)t1 - 128.f;   // k=1
            const float inv = rsqrtf(var2[f] + 1e-3f);
            const float cge = fmaxf(fmaf(S0 + S1 - mean2[f], inv, beta2[f]), 0.f);
            const float clt = fmaxf(fmaf(S1      - mean2[f], inv, beta2[f]), 0.f);
            g_add_ge[f] = cge + 128.f;       // fold "+128" of dot = 128 - 2*pc
            g_add_lt[f] = clt + 128.f;
            __threadfence();                 // release constants
        }
        __syncthreads();
        if (tid == 0) atomicExch(&g_flag, 1);
    }

    // ---------------- worker path (all 2048 blocks) ------------------------
    const int f0 = 4 * lane;
    const size_t row0 = (size_t)bid * 128 + (size_t)warp * 16;

    // Tight acquire-load spin (no nanosleep: its us-scale granularity was the
    // R7/R8 fixed-time penalty). Poll latency (~L2 round trip) is the backoff.
    if (tid == 0) {
        while (ld_acquire_gpu(&g_flag) == 0) { }
    }
    __syncthreads();

    // Row-invariant weights/constants into registers. These lines were never
    // touched by this block pre-flag, so L1 cannot hold stale copies; the
    // acquire load + syncthreads orders these reads after the producer's
    // release.
    const uint4 pw0 = *reinterpret_cast<const uint4*>(g_pw[f0 + 0]);
    const uint4 pw1 = *reinterpret_cast<const uint4*>(g_pw[f0 + 1]);
    const uint4 pw2 = *reinterpret_cast<const uint4*>(g_pw[f0 + 2]);
    const uint4 pw3 = *reinterpret_cast<const uint4*>(g_pw[f0 + 3]);
    const float4 age = *reinterpret_cast<const float4*>(&g_add_ge[f0]);
    const float4 alt = *reinterpret_cast<const float4*>(&g_add_lt[f0]);

    // Rows with t<16 exist only in warp 0 of every 64th block (8192/128=64).
    if (warp == 0 && (bid & 63) == 0) {
        do_rows<true >(x, out, row0, lane, pw0, pw1, pw2, pw3, age, alt);
    } else {
        do_rows<false>(x, out, row0, lane, pw0, pw1, pw2, pw3, age, alt);
    }

    // ---------------- reset protocol (deterministic graph replays) ---------
    if (tid == 0) {
        const int n = atomicAdd(&g_exit, 1);
        if (n == (int)gridDim.x - 1) {       // last block: restore sync state
            g_pcount = 0;
            g_flag   = 0;
            __threadfence();
            g_exit   = 0;
        }
    }
}

extern "C" void kernel_launch(void* const* d_in, const int* in_sizes, int n_in,
                              void* d_out, int out_size)
{
    // metadata order: x, w1, w2, w_sc, beta1, mean1, var1, beta2, mean2, var2
    const float* x     = (const float*)d_in[0];
    const float* w2    = (const float*)d_in[2];
    const float* w_sc  = (const float*)d_in[3];
    const float* beta2 = (const float*)d_in[7];
    const float* mean2 = (const float*)d_in[8];
    const float* var2  = (const float*)d_in[9];
    float* out = (float*)d_out;

    // 262144 rows / 128 rows per block = 2048 blocks, one launch total.
    resblock_fused<<<2048, 256>>>(x, out, w2, w_sc, beta2, mean2, var2);
}